// round 12
// baseline (speedup 1.0000x reference)
#include <cuda_runtime.h>
#include <cuda_fp16.h>
#include <cstdint>

#define BATCHN 64
#define FEAT   64
#define INF    64
#define NP     8
#define NCELL  256
#define NSYM   2048
#define NK2    9          // rfft half-plane: k2 in [0,8]
#define NFREQ  144        // 16 * 9
#define IPD    512        // INF * NP
#define FQD    512        // FEAT * NP

// -------- device scratch (no dynamic allocation allowed) --------
__device__ __half2 g_xf[(size_t)NFREQ * BATCHN * IPD];   // [k][b][ip] (re,im) fp16
__device__ __half2 g_kf[(size_t)NFREQ * IPD * FQD];      // [k][ip][fq] (~151 MB)
__device__ float2  g_yf[(size_t)NFREQ * BATCHN * FQD];   // [k][b][fq]
__device__ unsigned short g_pt16[NP * NSYM];

// cos/sin of 2*pi*m/16 — __device__ constexpr: folded to FFMA immediates
__device__ constexpr float KC16[16] = {
    1.0f,  0.92387953251f,  0.70710678119f,  0.38268343236f,
    0.0f, -0.38268343236f, -0.70710678119f, -0.92387953251f,
   -1.0f, -0.92387953251f, -0.70710678119f, -0.38268343236f,
    0.0f,  0.38268343236f,  0.70710678119f,  0.92387953251f };
__device__ constexpr float KS16[16] = {
    0.0f,  0.38268343236f,  0.70710678119f,  0.92387953251f,
    1.0f,  0.92387953251f,  0.70710678119f,  0.38268343236f,
    0.0f, -0.38268343236f, -0.70710678119f, -0.92387953251f,
   -1.0f, -0.92387953251f, -0.70710678119f, -0.38268343236f };

// runtime copies for k1/k4 (dynamic twiddle indexing there)
__constant__ float CTW16[16] = {
    1.0f,  0.92387953251f,  0.70710678119f,  0.38268343236f,
    0.0f, -0.38268343236f, -0.70710678119f, -0.92387953251f,
   -1.0f, -0.92387953251f, -0.70710678119f, -0.38268343236f,
    0.0f,  0.38268343236f,  0.70710678119f,  0.92387953251f };
__constant__ float STW16[16] = {
    0.0f,  0.38268343236f,  0.70710678119f,  0.92387953251f,
    1.0f,  0.92387953251f,  0.70710678119f,  0.38268343236f,
    0.0f, -0.38268343236f, -0.70710678119f, -0.92387953251f,
   -1.0f, -0.92387953251f, -0.70710678119f, -0.38268343236f };

// ============ K0: product_table (int32 OR int64) -> uint16 ============
__global__ __launch_bounds__(256) void k0_pt(const void* __restrict__ pt_raw) {
    __shared__ int odd_nonzero;
    const int* p32 = (const int*)pt_raw;
    int tid = threadIdx.x;
    if (tid == 0) odd_nonzero = 0;
    __syncthreads();
    int local = 0;
    for (int t = tid; t < (NP * NSYM) / 2; t += 256) local |= p32[2 * t + 1];
    if (local) odd_nonzero = 1;
    __syncthreads();
    if (odd_nonzero) {
        for (int t = tid; t < NP * NSYM; t += 256)
            g_pt16[t] = (unsigned short)p32[t];
    } else {
        const long long* p64 = (const long long*)pt_raw;
        for (int t = tid; t < NP * NSYM; t += 256)
            g_pt16[t] = (unsigned short)p64[t];
    }
}

// ============ K1: forward rfft2 of x images (half2 output) ============
__global__ __launch_bounds__(256) void k1_xfft(const float* __restrict__ x) {
    int bi = blockIdx.x;
    int b  = bi >> 6;
    int i  = bi & 63;
    __shared__ float  xs[NSYM];
    __shared__ float2 s1[NP * 145];
    __shared__ float2 tw[16];
    int tid = threadIdx.x;
    if (tid < 16) tw[tid] = make_float2(CTW16[tid], STW16[tid]);
    for (int t = tid; t < NSYM; t += 256) xs[t] = x[(size_t)bi * NSYM + t];
    __syncthreads();

    for (int idx = tid; idx < NP * 16 * NK2; idx += 256) {
        int p  = idx / 144;
        int r  = idx - p * 144;
        int c1 = r / 9;
        int k2 = r - c1 * 9;
        float2 acc = make_float2(0.f, 0.f);
#pragma unroll
        for (int c2 = 0; c2 < 16; c2++) {
            float  g = xs[(((c1 << 4) + c2) << 3) + p];
            float2 w = tw[(k2 * c2) & 15];
            acc.x += g * w.x;
            acc.y -= g * w.y;
        }
        s1[p * 145 + c1 * 9 + k2] = acc;
    }
    __syncthreads();

    for (int idx = tid; idx < NP * 16 * NK2; idx += 256) {
        int p  = idx & 7;
        int r  = idx >> 3;
        int k1 = r / 9;
        int k2 = r - k1 * 9;
        float2 acc = make_float2(0.f, 0.f);
#pragma unroll
        for (int c1 = 0; c1 < 16; c1++) {
            float2 v = s1[p * 145 + c1 * 9 + k2];
            float2 w = tw[(k1 * c1) & 15];
            acc.x += v.x * w.x + v.y * w.y;
            acc.y += v.y * w.x - v.x * w.y;
        }
        g_xf[((size_t)(k1 * 9 + k2) * BATCHN + b) * IPD + (i << 3) + p] =
            __floats2half2_rn(acc.x, acc.y);
    }
}

// ============ K2: gather + forward rfft2, register-blocked, fp16 out ============
// block = (f, i); per p: gather, stage1 (static k2-halves), stage2 (static k1-quarters)
#define K2S2BODY(K1Q)                                                        \
    _Pragma("unroll")                                                        \
    for (int c1 = 0; c1 < 16; c1++) {                                        \
        _Pragma("unroll")                                                    \
        for (int kk = 0; kk < 4; kk++) {                                     \
            const int id = ((((K1Q) * 4 + kk) * c1) & 15);                   \
            br[kk] += vv[c1].x * KC16[id] + vv[c1].y * KS16[id];             \
            bi[kk] += vv[c1].y * KC16[id] - vv[c1].x * KS16[id];             \
        }                                                                    \
    }

__global__ __launch_bounds__(256) void k2_kfft(const float* __restrict__ kern) {
    int fi = blockIdx.x, f = fi >> 6, i = fi & 63;
    __shared__ float krow[NSYM];
    __shared__ unsigned short ptp[NSYM];
    __shared__ float  g8[NP][264];     // [q][d], pad 264 (16B-aligned rows)
    __shared__ float2 s1[NP][145];     // [q][c1*9+k2]
    int tid = threadIdx.x;
    for (int t = tid; t < NSYM; t += 256) krow[t] = kern[(size_t)fi * NSYM + t];

    for (int p = 0; p < NP; p++) {
        __syncthreads();
        // ptp: 2048 u16 = 256 uint4, one per thread
        ((uint4*)ptp)[tid] = ((const uint4*)(g_pt16 + p * NSYM))[tid];
        __syncthreads();
        // gather: g8[q][d] = krow[pt[p][d*8+q]]
        for (int idx = tid; idx < NSYM; idx += 256)
            g8[idx & 7][idx >> 3] = krow[ptp[idx]];
        __syncthreads();
        // ---- stage1: thread = (k2half, q, c1); fully static twiddles ----
        {
            int k2h = tid >> 7, q = (tid >> 4) & 7, c1 = tid & 15;
            const float4* gp = (const float4*)&g8[q][c1 * 16];
            float4 ga = gp[0], gb = gp[1], gc = gp[2], gd = gp[3];
            float g[16] = { ga.x, ga.y, ga.z, ga.w, gb.x, gb.y, gb.z, gb.w,
                            gc.x, gc.y, gc.z, gc.w, gd.x, gd.y, gd.z, gd.w };
            if (k2h == 0) {
                float ar[5] = {0,0,0,0,0}, ai[5] = {0,0,0,0,0};
#pragma unroll
                for (int c2 = 0; c2 < 16; c2++) {
#pragma unroll
                    for (int t = 0; t < 5; t++) {
                        const int id = ((t * c2) & 15);
                        ar[t] += g[c2] * KC16[id];
                        ai[t] -= g[c2] * KS16[id];
                    }
                }
#pragma unroll
                for (int t = 0; t < 5; t++)
                    s1[q][c1 * 9 + t] = make_float2(ar[t], ai[t]);
            } else {
                float ar[4] = {0,0,0,0}, ai[4] = {0,0,0,0};
#pragma unroll
                for (int c2 = 0; c2 < 16; c2++) {
#pragma unroll
                    for (int t = 0; t < 4; t++) {
                        const int id = (((t + 5) * c2) & 15);
                        ar[t] += g[c2] * KC16[id];
                        ai[t] -= g[c2] * KS16[id];
                    }
                }
#pragma unroll
                for (int t = 0; t < 4; t++)
                    s1[q][c1 * 9 + 5 + t] = make_float2(ar[t], ai[t]);
            }
        }
        __syncthreads();
        // ---- stage2: item = (q, k2, k1-quarter); static twiddles per branch ----
        for (int u = tid; u < 288; u += 256) {
            int q = u & 7, v = u >> 3;
            int k2 = v % 9, k1q = v / 9;
            float2 vv[16];
#pragma unroll
            for (int c1 = 0; c1 < 16; c1++) vv[c1] = s1[q][c1 * 9 + k2];
            float br[4] = {0,0,0,0}, bi[4] = {0,0,0,0};
            if      (k1q == 0) { K2S2BODY(0) }
            else if (k1q == 1) { K2S2BODY(1) }
            else if (k1q == 2) { K2S2BODY(2) }
            else               { K2S2BODY(3) }
#pragma unroll
            for (int kk = 0; kk < 4; kk++) {
                int k1 = k1q * 4 + kk;
                g_kf[((size_t)(k1 * 9 + k2) * IPD + (i << 3) + p) * FQD + (f << 3) + q] =
                    __floats2half2_rn(br[kk], bi[kk]);
            }
        }
    }
}

// ============ K3: per-frequency complex GEMM, fp16 mma (m16n8k16) ============
// grid = (144 freqs, 4 N-tiles of 128). block 256 = 8 warps (4 M x 2 N).
__device__ __forceinline__ void mma16(float* d, const uint32_t* a,
                                      uint32_t b0, uint32_t b1) {
    asm volatile(
        "mma.sync.aligned.m16n8k16.row.col.f32.f16.f16.f32 "
        "{%0,%1,%2,%3}, {%4,%5,%6,%7}, {%8,%9}, {%0,%1,%2,%3};\n"
        : "+f"(d[0]), "+f"(d[1]), "+f"(d[2]), "+f"(d[3])
        : "r"(a[0]), "r"(a[1]), "r"(a[2]), "r"(a[3]), "r"(b0), "r"(b1));
}

__global__ __launch_bounds__(256) void k3_gemm_hmma() {
    int kidx = blockIdx.x;
    int n0   = blockIdx.y << 7;
    __shared__ __align__(16) __half2 Xs[64][20];    // [b][k] interleaved (re,im)
    __shared__ __align__(16) __half2 Ws[16][132];   // [k][n] interleaved

    int tid = threadIdx.x, wid = tid >> 5, lane = tid & 31;
    int wm = (wid & 3) << 4, wn = (wid >> 2) << 6;
    int gid = lane >> 2, tig = lane & 3;

    float accr[8][4], acci[8][4];
#pragma unroll
    for (int j = 0; j < 8; j++)
#pragma unroll
        for (int c = 0; c < 4; c++) { accr[j][c] = 0.f; acci[j][c] = 0.f; }

    for (int k0 = 0; k0 < IPD; k0 += 16) {
        // stage X: 64 rows x 4 uint4 (16 half2 per row)
        {
            int b = tid >> 2, seg = tid & 3;
            uint4 v = *(const uint4*)&g_xf[(size_t)kidx * BATCHN * IPD + (size_t)b * IPD + k0 + seg * 4];
            *(uint4*)&Xs[b][seg * 4] = v;
        }
        // stage W: 16 rows x 32 uint4
#pragma unroll
        for (int it = 0; it < 2; it++) {
            int v  = tid + (it << 8);
            int kk = v >> 5, seg = v & 31;
            uint4 w = *(const uint4*)&g_kf[((size_t)kidx * IPD + k0 + kk) * FQD + n0 + seg * 4];
            *(uint4*)&Ws[kk][seg * 4] = w;
        }
        __syncthreads();

        // A fragments (re/im split via byte_perm)
        uint32_t arf[4], aif[4];
#pragma unroll
        for (int m = 0; m < 4; m++) {
            int row  = wm + gid + (m & 1) * 8;
            int kpos = 2 * tig + (m >> 1) * 8;
            uint2 lh = *(const uint2*)&Xs[row][kpos];   // (k, k+1) interleaved
            arf[m] = __byte_perm(lh.x, lh.y, 0x5410);   // re(k), re(k+1)
            aif[m] = __byte_perm(lh.x, lh.y, 0x7632);   // im(k), im(k+1)
        }
#pragma unroll
        for (int j = 0; j < 8; j++) {
            int col = wn + (j << 3) + gid;
            uint32_t v0 = *(const uint32_t*)&Ws[2 * tig][col];
            uint32_t v1 = *(const uint32_t*)&Ws[2 * tig + 1][col];
            uint32_t v2 = *(const uint32_t*)&Ws[2 * tig + 8][col];
            uint32_t v3 = *(const uint32_t*)&Ws[2 * tig + 9][col];
            uint32_t br0 = __byte_perm(v0, v1, 0x5410), bi0 = __byte_perm(v0, v1, 0x7632);
            uint32_t br1 = __byte_perm(v2, v3, 0x5410), bi1 = __byte_perm(v2, v3, 0x7632);
            uint32_t bn0 = bi0 ^ 0x80008000u, bn1 = bi1 ^ 0x80008000u;   // -Wi
            mma16(accr[j], arf, br0, br1);   // Yr += Xr*Wr
            mma16(accr[j], aif, bn0, bn1);   // Yr += Xi*(-Wi)
            mma16(acci[j], arf, bi0, bi1);   // Yi += Xr*Wi
            mma16(acci[j], aif, br0, br1);   // Yi += Xi*Wr
        }
        __syncthreads();
    }

    float2* Yg = g_yf + (size_t)kidx * BATCHN * FQD;
#pragma unroll
    for (int j = 0; j < 8; j++) {
        int nbase = n0 + wn + (j << 3) + 2 * tig;
        int r0 = wm + gid;
        int r1 = wm + gid + 8;
        Yg[(size_t)r0 * FQD + nbase]     = make_float2(accr[j][0], acci[j][0]);
        Yg[(size_t)r0 * FQD + nbase + 1] = make_float2(accr[j][1], acci[j][1]);
        Yg[(size_t)r1 * FQD + nbase]     = make_float2(accr[j][2], acci[j][2]);
        Yg[(size_t)r1 * FQD + nbase + 1] = make_float2(accr[j][3], acci[j][3]);
    }
}

// ============ K4: inverse rfft2 (hermitian weights) + bias ============
__global__ __launch_bounds__(256) void k4_inv(const float* __restrict__ bias,
                                              float* __restrict__ out) {
    int bf = blockIdx.x;
    int b  = bf >> 6;
    int f  = bf & 63;
    __shared__ float2 ys[NP * NFREQ];
    __shared__ float2 T[NP * 145];
    __shared__ float2 tw[16];
    int tid = threadIdx.x;
    if (tid < 16) tw[tid] = make_float2(CTW16[tid], STW16[tid]);

    for (int idx = tid; idx < NP * NFREQ; idx += 256) {
        int kidx = idx >> 3;
        int q    = idx & 7;
        ys[q * NFREQ + kidx] =
            g_yf[((size_t)kidx * BATCHN + b) * FQD + (f << 3) + q];
    }
    __syncthreads();

    for (int idx = tid; idx < NP * 16 * NK2; idx += 256) {
        int q  = idx / 144;
        int r  = idx - q * 144;
        int c1 = r / 9;
        int k2 = r - c1 * 9;
        float2 acc = make_float2(0.f, 0.f);
#pragma unroll
        for (int k1 = 0; k1 < 16; k1++) {
            float2 v = ys[q * NFREQ + k1 * 9 + k2];
            float2 w = tw[(k1 * c1) & 15];
            acc.x += v.x * w.x - v.y * w.y;
            acc.y += v.x * w.y + v.y * w.x;
        }
        T[q * 145 + c1 * 9 + k2] = acc;
    }
    __syncthreads();

    float bv = bias[f];
    for (int idx = tid; idx < NSYM; idx += 256) {
        int c  = idx >> 3;
        int q  = idx & 7;
        int c1 = c >> 4;
        int c2 = c & 15;
        float acc = 0.f;
#pragma unroll
        for (int k2 = 0; k2 < NK2; k2++) {
            float2 v  = T[q * 145 + c1 * 9 + k2];
            float2 w  = tw[(k2 * c2) & 15];
            float  wt = (k2 == 0 || k2 == 8) ? 1.f : 2.f;
            acc += wt * (v.x * w.x - v.y * w.y);
        }
        out[(size_t)bf * NSYM + idx] = acc * (1.f / 256.f) + bv;
    }
}

// ============ launch ============
extern "C" void kernel_launch(void* const* d_in, const int* in_sizes, int n_in,
                              void* d_out, int out_size) {
    const float* x    = (const float*)d_in[0];
    const float* kern = (const float*)d_in[1];
    const float* bias = (const float*)d_in[2];
    const void*  pt   = d_in[3];              // int32 or int64 — k0 autodetects
    float*       out  = (float*)d_out;

    k0_pt<<<1, 256>>>(pt);
    k1_xfft<<<BATCHN * INF, 256>>>(x);
    k2_kfft<<<FEAT * INF, 256>>>(kern);
    dim3 g3(NFREQ, FQD / 128);
    k3_gemm_hmma<<<g3, 256>>>();
    k4_inv<<<BATCHN * FEAT, 256>>>(bias, out);
}

// round 13
// speedup vs baseline: 1.1829x; 1.1829x over previous
#include <cuda_runtime.h>
#include <cuda_fp16.h>
#include <cstdint>

#define BATCHN 64
#define FEAT   64
#define INF    64
#define NP     8
#define NCELL  256
#define NSYM   2048
#define NK2    9          // rfft half-plane: k2 in [0,8]
#define NFREQ  144        // 16 * 9
#define IPD    512        // INF * NP
#define FQD    512        // FEAT * NP

// -------- device scratch (no dynamic allocation allowed) --------
__device__ __half2 g_xf[(size_t)NFREQ * BATCHN * IPD];   // [k][b][ip] (re,im) fp16
__device__ __half2 g_kf[(size_t)NFREQ * IPD * FQD];      // [k][ip][fq] (~151 MB)
__device__ float2  g_yf[(size_t)NFREQ * BATCHN * FQD];   // [k][b][fq]
__device__ unsigned short g_pt16[NP * NSYM];

// cos/sin of 2*pi*m/16 — __device__ constexpr: folded to FFMA immediates
__device__ constexpr float KC16[16] = {
    1.0f,  0.92387953251f,  0.70710678119f,  0.38268343236f,
    0.0f, -0.38268343236f, -0.70710678119f, -0.92387953251f,
   -1.0f, -0.92387953251f, -0.70710678119f, -0.38268343236f,
    0.0f,  0.38268343236f,  0.70710678119f,  0.92387953251f };
__device__ constexpr float KS16[16] = {
    0.0f,  0.38268343236f,  0.70710678119f,  0.92387953251f,
    1.0f,  0.92387953251f,  0.70710678119f,  0.38268343236f,
    0.0f, -0.38268343236f, -0.70710678119f, -0.92387953251f,
   -1.0f, -0.38268343236f, -0.70710678119f, -0.92387953251f };
// NOTE: row above must mirror sin table exactly; fixed below (see KS16F check)

// runtime copies for k4 stageB hoist (dynamic index, loaded once per thread)
__constant__ float CTW16[16] = {
    1.0f,  0.92387953251f,  0.70710678119f,  0.38268343236f,
    0.0f, -0.38268343236f, -0.70710678119f, -0.92387953251f,
   -1.0f, -0.92387953251f, -0.70710678119f, -0.38268343236f,
    0.0f,  0.38268343236f,  0.70710678119f,  0.92387953251f };
__constant__ float STW16[16] = {
    0.0f,  0.38268343236f,  0.70710678119f,  0.92387953251f,
    1.0f,  0.92387953251f,  0.70710678119f,  0.38268343236f,
    0.0f, -0.38268343236f, -0.70710678119f, -0.92387953251f,
   -1.0f, -0.92387953251f, -0.70710678119f, -0.38268343236f };

// ============ K0: product_table (int32 OR int64) -> uint16 ============
__global__ __launch_bounds__(256) void k0_pt(const void* __restrict__ pt_raw) {
    __shared__ int odd_nonzero;
    const int* p32 = (const int*)pt_raw;
    int tid = threadIdx.x;
    if (tid == 0) odd_nonzero = 0;
    __syncthreads();
    int local = 0;
    for (int t = tid; t < (NP * NSYM) / 2; t += 256) local |= p32[2 * t + 1];
    if (local) odd_nonzero = 1;
    __syncthreads();
    if (odd_nonzero) {
        for (int t = tid; t < NP * NSYM; t += 256)
            g_pt16[t] = (unsigned short)p32[t];
    } else {
        const long long* p64 = (const long long*)pt_raw;
        for (int t = tid; t < NP * NSYM; t += 256)
            g_pt16[t] = (unsigned short)p64[t];
    }
}

// Shared DFT bodies (fully static twiddle indices -> literals after unroll)
#define DFT_S2_FWD(K1Q)                                                      \
    _Pragma("unroll")                                                        \
    for (int c1 = 0; c1 < 16; c1++) {                                        \
        _Pragma("unroll")                                                    \
        for (int kk = 0; kk < 4; kk++) {                                     \
            const int id = ((((K1Q) * 4 + kk) * c1) & 15);                   \
            br[kk] += vv[c1].x * KC16[id] + vv[c1].y * KS16F[id];            \
            bi[kk] += vv[c1].y * KC16[id] - vv[c1].x * KS16F[id];            \
        }                                                                    \
    }

#define DFT_SA_INV(C1Q)                                                      \
    _Pragma("unroll")                                                        \
    for (int k1 = 0; k1 < 16; k1++) {                                        \
        _Pragma("unroll")                                                    \
        for (int kk = 0; kk < 4; kk++) {                                     \
            const int id = ((((C1Q) * 4 + kk) * k1) & 15);                   \
            br[kk] += vv[k1].x * KC16[id] - vv[k1].y * KS16F[id];            \
            bi[kk] += vv[k1].y * KC16[id] + vv[k1].x * KS16F[id];            \
        }                                                                    \
    }

// correct sin table (authoritative; KS16 above unused)
__device__ constexpr float KS16F[16] = {
    0.0f,  0.38268343236f,  0.70710678119f,  0.92387953251f,
    1.0f,  0.92387953251f,  0.70710678119f,  0.38268343236f,
    0.0f, -0.38268343236f, -0.70710678119f, -0.92387953251f,
   -1.0f, -0.92387953251f, -0.70710678119f, -0.38268343236f };

// ============ K1: forward rfft2 of x images, static twiddles ============
// block = (b, i); 8 images (p) handled at once
__global__ __launch_bounds__(256) void k1_xfft(const float* __restrict__ x) {
    int bi = blockIdx.x;
    int b  = bi >> 6;
    int i  = bi & 63;
    __shared__ float  xs2[NP][264];    // [p][d], padded rows (16B-aligned)
    __shared__ float2 s1[NP][145];     // [p][c1*9+k2]
    int tid = threadIdx.x;

    // load + transpose: thread tid holds all 8 p for d = tid
    {
        const float4* xg = (const float4*)(x + (size_t)bi * NSYM);
        float4 a = xg[tid * 2], c = xg[tid * 2 + 1];
        xs2[0][tid] = a.x; xs2[1][tid] = a.y; xs2[2][tid] = a.z; xs2[3][tid] = a.w;
        xs2[4][tid] = c.x; xs2[5][tid] = c.y; xs2[6][tid] = c.z; xs2[7][tid] = c.w;
    }
    __syncthreads();

    // stage1: thread = (k2half, p, c1)
    {
        int k2h = tid >> 7, p = (tid >> 4) & 7, c1 = tid & 15;
        const float4* gp = (const float4*)&xs2[p][c1 * 16];
        float4 ga = gp[0], gb = gp[1], gc = gp[2], gd = gp[3];
        float g[16] = { ga.x, ga.y, ga.z, ga.w, gb.x, gb.y, gb.z, gb.w,
                        gc.x, gc.y, gc.z, gc.w, gd.x, gd.y, gd.z, gd.w };
        if (k2h == 0) {
            float ar[5] = {0,0,0,0,0}, ai[5] = {0,0,0,0,0};
#pragma unroll
            for (int c2 = 0; c2 < 16; c2++)
#pragma unroll
                for (int t = 0; t < 5; t++) {
                    const int id = ((t * c2) & 15);
                    ar[t] += g[c2] * KC16[id];
                    ai[t] -= g[c2] * KS16F[id];
                }
#pragma unroll
            for (int t = 0; t < 5; t++) s1[p][c1 * 9 + t] = make_float2(ar[t], ai[t]);
        } else {
            float ar[4] = {0,0,0,0}, ai[4] = {0,0,0,0};
#pragma unroll
            for (int c2 = 0; c2 < 16; c2++)
#pragma unroll
                for (int t = 0; t < 4; t++) {
                    const int id = (((t + 5) * c2) & 15);
                    ar[t] += g[c2] * KC16[id];
                    ai[t] -= g[c2] * KS16F[id];
                }
#pragma unroll
            for (int t = 0; t < 4; t++) s1[p][c1 * 9 + 5 + t] = make_float2(ar[t], ai[t]);
        }
    }
    __syncthreads();

    // stage2: item = (p, k2, k1-quarter)
    for (int u = tid; u < 288; u += 256) {
        int p = u & 7, v = u >> 3;
        int k2 = v % 9, k1q = v / 9;
        float2 vv[16];
#pragma unroll
        for (int c1 = 0; c1 < 16; c1++) vv[c1] = s1[p][c1 * 9 + k2];
        float br[4] = {0,0,0,0}, bi[4] = {0,0,0,0};
        if      (k1q == 0) { DFT_S2_FWD(0) }
        else if (k1q == 1) { DFT_S2_FWD(1) }
        else if (k1q == 2) { DFT_S2_FWD(2) }
        else               { DFT_S2_FWD(3) }
#pragma unroll
        for (int kk = 0; kk < 4; kk++) {
            int k1 = k1q * 4 + kk;
            g_xf[((size_t)(k1 * 9 + k2) * BATCHN + b) * IPD + (i << 3) + p] =
                __floats2half2_rn(br[kk], bi[kk]);
        }
    }
}

// ============ K2: gather + forward rfft2, p flattened into grid ============
// grid = 64*64*8 blocks, one (f, i, p) each; 3 syncs per block.
__global__ __launch_bounds__(256) void k2_kfft(const float* __restrict__ kern) {
    int bx = blockIdx.x;
    int fi = bx >> 3, p = bx & 7;
    int f  = fi >> 6, i = fi & 63;
    __shared__ float krow[NSYM];
    __shared__ unsigned short ptp[NSYM];
    __shared__ float  g8[NP][264];
    __shared__ float2 s1[NP][145];
    int tid = threadIdx.x;

    // loads: krow (2 float4/thread) + ptp (1 uint4/thread)
    {
        const float4* kg = (const float4*)(kern + (size_t)fi * NSYM);
        ((float4*)krow)[tid * 2]     = kg[tid * 2];
        ((float4*)krow)[tid * 2 + 1] = kg[tid * 2 + 1];
        ((uint4*)ptp)[tid] = ((const uint4*)(g_pt16 + p * NSYM))[tid];
    }
    __syncthreads();

    // gather: g8[q][d] = krow[pt[p][d*8+q]]
    for (int idx = tid; idx < NSYM; idx += 256)
        g8[idx & 7][idx >> 3] = krow[ptp[idx]];
    __syncthreads();

    // stage1: thread = (k2half, q, c1)
    {
        int k2h = tid >> 7, q = (tid >> 4) & 7, c1 = tid & 15;
        const float4* gp = (const float4*)&g8[q][c1 * 16];
        float4 ga = gp[0], gb = gp[1], gc = gp[2], gd = gp[3];
        float g[16] = { ga.x, ga.y, ga.z, ga.w, gb.x, gb.y, gb.z, gb.w,
                        gc.x, gc.y, gc.z, gc.w, gd.x, gd.y, gd.z, gd.w };
        if (k2h == 0) {
            float ar[5] = {0,0,0,0,0}, ai[5] = {0,0,0,0,0};
#pragma unroll
            for (int c2 = 0; c2 < 16; c2++)
#pragma unroll
                for (int t = 0; t < 5; t++) {
                    const int id = ((t * c2) & 15);
                    ar[t] += g[c2] * KC16[id];
                    ai[t] -= g[c2] * KS16F[id];
                }
#pragma unroll
            for (int t = 0; t < 5; t++) s1[q][c1 * 9 + t] = make_float2(ar[t], ai[t]);
        } else {
            float ar[4] = {0,0,0,0}, ai[4] = {0,0,0,0};
#pragma unroll
            for (int c2 = 0; c2 < 16; c2++)
#pragma unroll
                for (int t = 0; t < 4; t++) {
                    const int id = (((t + 5) * c2) & 15);
                    ar[t] += g[c2] * KC16[id];
                    ai[t] -= g[c2] * KS16F[id];
                }
#pragma unroll
            for (int t = 0; t < 4; t++) s1[q][c1 * 9 + 5 + t] = make_float2(ar[t], ai[t]);
        }
    }
    __syncthreads();

    // stage2: item = (q, k2, k1-quarter)
    for (int u = tid; u < 288; u += 256) {
        int q = u & 7, v = u >> 3;
        int k2 = v % 9, k1q = v / 9;
        float2 vv[16];
#pragma unroll
        for (int c1 = 0; c1 < 16; c1++) vv[c1] = s1[q][c1 * 9 + k2];
        float br[4] = {0,0,0,0}, bi[4] = {0,0,0,0};
        if      (k1q == 0) { DFT_S2_FWD(0) }
        else if (k1q == 1) { DFT_S2_FWD(1) }
        else if (k1q == 2) { DFT_S2_FWD(2) }
        else               { DFT_S2_FWD(3) }
#pragma unroll
        for (int kk = 0; kk < 4; kk++) {
            int k1 = k1q * 4 + kk;
            g_kf[((size_t)(k1 * 9 + k2) * IPD + (i << 3) + p) * FQD + (f << 3) + q] =
                __floats2half2_rn(br[kk], bi[kk]);
        }
    }
}

// ============ K3: per-frequency complex GEMM, fp16 mma (m16n8k16) ============
__device__ __forceinline__ void mma16(float* d, const uint32_t* a,
                                      uint32_t b0, uint32_t b1) {
    asm volatile(
        "mma.sync.aligned.m16n8k16.row.col.f32.f16.f16.f32 "
        "{%0,%1,%2,%3}, {%4,%5,%6,%7}, {%8,%9}, {%0,%1,%2,%3};\n"
        : "+f"(d[0]), "+f"(d[1]), "+f"(d[2]), "+f"(d[3])
        : "r"(a[0]), "r"(a[1]), "r"(a[2]), "r"(a[3]), "r"(b0), "r"(b1));
}

__global__ __launch_bounds__(256) void k3_gemm_hmma() {
    int kidx = blockIdx.x;
    int n0   = blockIdx.y << 7;
    __shared__ __align__(16) __half2 Xs[64][20];
    __shared__ __align__(16) __half2 Ws[16][132];

    int tid = threadIdx.x, wid = tid >> 5, lane = tid & 31;
    int wm = (wid & 3) << 4, wn = (wid >> 2) << 6;
    int gid = lane >> 2, tig = lane & 3;

    float accr[8][4], acci[8][4];
#pragma unroll
    for (int j = 0; j < 8; j++)
#pragma unroll
        for (int c = 0; c < 4; c++) { accr[j][c] = 0.f; acci[j][c] = 0.f; }

    for (int k0 = 0; k0 < IPD; k0 += 16) {
        {
            int b = tid >> 2, seg = tid & 3;
            uint4 v = *(const uint4*)&g_xf[(size_t)kidx * BATCHN * IPD + (size_t)b * IPD + k0 + seg * 4];
            *(uint4*)&Xs[b][seg * 4] = v;
        }
#pragma unroll
        for (int it = 0; it < 2; it++) {
            int v  = tid + (it << 8);
            int kk = v >> 5, seg = v & 31;
            uint4 w = *(const uint4*)&g_kf[((size_t)kidx * IPD + k0 + kk) * FQD + n0 + seg * 4];
            *(uint4*)&Ws[kk][seg * 4] = w;
        }
        __syncthreads();

        uint32_t arf[4], aif[4];
#pragma unroll
        for (int m = 0; m < 4; m++) {
            int row  = wm + gid + (m & 1) * 8;
            int kpos = 2 * tig + (m >> 1) * 8;
            uint2 lh = *(const uint2*)&Xs[row][kpos];
            arf[m] = __byte_perm(lh.x, lh.y, 0x5410);
            aif[m] = __byte_perm(lh.x, lh.y, 0x7632);
        }
#pragma unroll
        for (int j = 0; j < 8; j++) {
            int col = wn + (j << 3) + gid;
            uint32_t v0 = *(const uint32_t*)&Ws[2 * tig][col];
            uint32_t v1 = *(const uint32_t*)&Ws[2 * tig + 1][col];
            uint32_t v2 = *(const uint32_t*)&Ws[2 * tig + 8][col];
            uint32_t v3 = *(const uint32_t*)&Ws[2 * tig + 9][col];
            uint32_t br0 = __byte_perm(v0, v1, 0x5410), bi0 = __byte_perm(v0, v1, 0x7632);
            uint32_t br1 = __byte_perm(v2, v3, 0x5410), bi1 = __byte_perm(v2, v3, 0x7632);
            uint32_t bn0 = bi0 ^ 0x80008000u, bn1 = bi1 ^ 0x80008000u;
            mma16(accr[j], arf, br0, br1);
            mma16(accr[j], aif, bn0, bn1);
            mma16(acci[j], arf, bi0, bi1);
            mma16(acci[j], aif, br0, br1);
        }
        __syncthreads();
    }

    float2* Yg = g_yf + (size_t)kidx * BATCHN * FQD;
#pragma unroll
    for (int j = 0; j < 8; j++) {
        int nbase = n0 + wn + (j << 3) + 2 * tig;
        int r0 = wm + gid;
        int r1 = wm + gid + 8;
        Yg[(size_t)r0 * FQD + nbase]     = make_float2(accr[j][0], acci[j][0]);
        Yg[(size_t)r0 * FQD + nbase + 1] = make_float2(accr[j][1], acci[j][1]);
        Yg[(size_t)r1 * FQD + nbase]     = make_float2(accr[j][2], acci[j][2]);
        Yg[(size_t)r1 * FQD + nbase + 1] = make_float2(accr[j][3], acci[j][3]);
    }
}

// ============ K4: inverse rfft2 + bias; static stageA, hoisted stageB ============
__global__ __launch_bounds__(256) void k4_inv(const float* __restrict__ bias,
                                              float* __restrict__ out) {
    int bf = blockIdx.x;
    int b  = bf >> 6;
    int f  = bf & 63;
    __shared__ float2 ys[NP][145];   // [q][kidx], padded row (290 words % 32 = 2)
    __shared__ float2 T[NP][145];    // [q][c1*9+k2]
    __shared__ float2 tw[16];
    int tid = threadIdx.x;
    if (tid < 16) tw[tid] = make_float2(CTW16[tid], STW16[tid]);

    for (int idx = tid; idx < NP * NFREQ; idx += 256) {
        int kidx = idx >> 3;
        int q    = idx & 7;
        ys[q][kidx] = g_yf[((size_t)kidx * BATCHN + b) * FQD + (f << 3) + q];
    }
    __syncthreads();

    // stageA: item = (q, k2, c1-quarter): T[c1][k2] = sum_k1 Y e^{+i 2pi k1 c1/16}
    for (int u = tid; u < 288; u += 256) {
        int q = u & 7, v = u >> 3;
        int k2 = v % 9, c1q = v / 9;
        float2 vv[16];
#pragma unroll
        for (int k1 = 0; k1 < 16; k1++) vv[k1] = ys[q][k1 * 9 + k2];
        float br[4] = {0,0,0,0}, bi[4] = {0,0,0,0};
        if      (c1q == 0) { DFT_SA_INV(0) }
        else if (c1q == 1) { DFT_SA_INV(1) }
        else if (c1q == 2) { DFT_SA_INV(2) }
        else               { DFT_SA_INV(3) }
#pragma unroll
        for (int kk = 0; kk < 4; kk++)
            T[q][(c1q * 4 + kk) * 9 + k2] = make_float2(br[kk], bi[kk]);
    }
    __syncthreads();

    // stageB: c2 and q are per-thread invariants across the 8 items ->
    // hoist 9 weighted twiddles into registers, inner loop is pure FMA.
    float bv = bias[f];
    {
        int q  = tid & 7;
        int c2 = (tid >> 3) & 15;
        float wc[9], ws[9];
#pragma unroll
        for (int k2 = 0; k2 < NK2; k2++) {
            float2 w = tw[(k2 * c2) & 15];
            float wt = (k2 == 0 || k2 == 8) ? (1.f / 256.f) : (2.f / 256.f);
            wc[k2] = wt * w.x;
            ws[k2] = wt * w.y;
        }
#pragma unroll
        for (int u = 0; u < 8; u++) {
            int c1 = u * 2 + (tid >> 7);
            float acc = bv;
#pragma unroll
            for (int k2 = 0; k2 < NK2; k2++) {
                float2 v = T[q][c1 * 9 + k2];
                acc += v.x * wc[k2] - v.y * ws[k2];
            }
            out[(size_t)bf * NSYM + u * 256 + tid] = acc;
        }
    }
}

// ============ launch ============
extern "C" void kernel_launch(void* const* d_in, const int* in_sizes, int n_in,
                              void* d_out, int out_size) {
    const float* x    = (const float*)d_in[0];
    const float* kern = (const float*)d_in[1];
    const float* bias = (const float*)d_in[2];
    const void*  pt   = d_in[3];              // int32 or int64 — k0 autodetects
    float*       out  = (float*)d_out;

    k0_pt<<<1, 256>>>(pt);
    k1_xfft<<<BATCHN * INF, 256>>>(x);
    k2_kfft<<<FEAT * INF * NP, 256>>>(kern);
    dim3 g3(NFREQ, FQD / 128);
    k3_gemm_hmma<<<g3, 256>>>();
    k4_inv<<<BATCHN * FEAT, 256>>>(bias, out);
}

// round 14
// speedup vs baseline: 1.7589x; 1.4870x over previous
#include <cuda_runtime.h>
#include <cuda_fp16.h>
#include <cstdint>

#define BATCHN 64
#define FEAT   64
#define INF    64
#define NP     8
#define NCELL  256
#define NSYM   2048
#define NK2    9          // rfft half-plane: k2 in [0,8]
#define NFREQ  144        // 16 * 9
#define IPD    512        // INF * NP
#define FQD    512        // FEAT * NP

// -------- device scratch (no dynamic allocation allowed) --------
__device__ __half2 g_xf[(size_t)NFREQ * BATCHN * IPD];   // [k][b][ip]
__device__ __half2 g_kf[(size_t)NFREQ * IPD * FQD];      // [k][ip][fq] (~151 MB)
__device__ float2  g_yf[(size_t)NFREQ * BATCHN * FQD];   // [k][b][fq]
__device__ unsigned short g_pt16[NP * NSYM];

// cos/sin of 2*pi*m/16 — __device__ constexpr: folded to FFMA immediates
__device__ constexpr float KC16[16] = {
    1.0f,  0.92387953251f,  0.70710678119f,  0.38268343236f,
    0.0f, -0.38268343236f, -0.70710678119f, -0.92387953251f,
   -1.0f, -0.92387953251f, -0.70710678119f, -0.38268343236f,
    0.0f,  0.38268343236f,  0.70710678119f,  0.92387953251f };
__device__ constexpr float KS16F[16] = {
    0.0f,  0.38268343236f,  0.70710678119f,  0.92387953251f,
    1.0f,  0.92387953251f,  0.70710678119f,  0.38268343236f,
    0.0f, -0.38268343236f, -0.70710678119f, -0.92387953251f,
   -1.0f, -0.92387953251f, -0.70710678119f, -0.38268343236f };

// runtime twiddles for k4 stageB hoist
__constant__ float CTW16[16] = {
    1.0f,  0.92387953251f,  0.70710678119f,  0.38268343236f,
    0.0f, -0.38268343236f, -0.70710678119f, -0.92387953251f,
   -1.0f, -0.92387953251f, -0.70710678119f, -0.38268343236f,
    0.0f,  0.38268343236f,  0.70710678119f,  0.92387953251f };
__constant__ float STW16[16] = {
    0.0f,  0.38268343236f,  0.70710678119f,  0.92387953251f,
    1.0f,  0.92387953251f,  0.70710678119f,  0.38268343236f,
    0.0f, -0.38268343236f, -0.70710678119f, -0.92387953251f,
   -1.0f, -0.92387953251f, -0.70710678119f, -0.38268343236f };

// ---------------- complex helpers + 16-point FFT (static twiddles) ----------
__device__ __forceinline__ float2 cadd(float2 a, float2 b){ return make_float2(a.x+b.x, a.y+b.y); }
__device__ __forceinline__ float2 csub(float2 a, float2 b){ return make_float2(a.x-b.x, a.y-b.y); }
__device__ __forceinline__ float2 cwf(float2 v, int m){   // v * e^{-2pi i m/16}
    float C = KC16[m & 15], S = KS16F[m & 15];
    return make_float2(v.x*C + v.y*S, v.y*C - v.x*S);
}
__device__ __forceinline__ float2 cwi(float2 v, int m){   // v * e^{+2pi i m/16}
    float C = KC16[m & 15], S = KS16F[m & 15];
    return make_float2(v.x*C - v.y*S, v.y*C + v.x*S);
}
__device__ __forceinline__ void dft4f(float2 a, float2 b, float2 c, float2 d, float2* A){
    float2 t0=cadd(a,c), t1=csub(a,c), t2=cadd(b,d), t3=csub(b,d);
    A[0]=cadd(t0,t2); A[2]=csub(t0,t2);
    A[1]=make_float2(t1.x + t3.y, t1.y - t3.x);   // t1 - i*t3
    A[3]=make_float2(t1.x - t3.y, t1.y + t3.x);   // t1 + i*t3
}
__device__ __forceinline__ void dft4i(float2 a, float2 b, float2 c, float2 d, float2* A){
    float2 t0=cadd(a,c), t1=csub(a,c), t2=cadd(b,d), t3=csub(b,d);
    A[0]=cadd(t0,t2); A[2]=csub(t0,t2);
    A[1]=make_float2(t1.x - t3.y, t1.y + t3.x);   // t1 + i*t3
    A[3]=make_float2(t1.x + t3.y, t1.y - t3.x);   // t1 - i*t3
}
// 16-point DFT: INV=false -> e^{-2pi i nk/16}; INV=true -> e^{+...} (unscaled)
template<bool INV>
__device__ __forceinline__ void cfft16(const float2* x, float2* X){
    float2 A[4], B[4], C4[4], D[4];
    if (!INV) {
        dft4f(x[0],x[4],x[8],x[12],A);  dft4f(x[2],x[6],x[10],x[14],B);
        dft4f(x[1],x[5],x[9],x[13],C4); dft4f(x[3],x[7],x[11],x[15],D);
    } else {
        dft4i(x[0],x[4],x[8],x[12],A);  dft4i(x[2],x[6],x[10],x[14],B);
        dft4i(x[1],x[5],x[9],x[13],C4); dft4i(x[3],x[7],x[11],x[15],D);
    }
    float2 E[8], O[8];
#pragma unroll
    for (int k = 0; k < 8; k++) {
        float2 tb = INV ? cwi(B[k&3], (2*k)&15) : cwf(B[k&3], (2*k)&15);
        float2 td = INV ? cwi(D[k&3], (2*k)&15) : cwf(D[k&3], (2*k)&15);
        E[k] = cadd(A[k&3], tb);
        O[k] = cadd(C4[k&3], td);
    }
#pragma unroll
    for (int k = 0; k < 16; k++) {
        float2 to = INV ? cwi(O[k&7], k&15) : cwf(O[k&7], k&15);
        X[k] = cadd(E[k&7], to);
    }
}

// ============ K0: product_table (int32 OR int64) -> uint16 ============
__global__ __launch_bounds__(256) void k0_pt(const void* __restrict__ pt_raw) {
    __shared__ int odd_nonzero;
    const int* p32 = (const int*)pt_raw;
    int tid = threadIdx.x;
    if (tid == 0) odd_nonzero = 0;
    __syncthreads();
    int local = 0;
    for (int t = tid; t < (NP * NSYM) / 2; t += 256) local |= p32[2 * t + 1];
    if (local) odd_nonzero = 1;
    __syncthreads();
    if (odd_nonzero) {
        for (int t = tid; t < NP * NSYM; t += 256)
            g_pt16[t] = (unsigned short)p32[t];
    } else {
        const long long* p64 = (const long long*)pt_raw;
        for (int t = tid; t < NP * NSYM; t += 256)
            g_pt16[t] = (unsigned short)p64[t];
    }
}

// ============ K1: forward rfft2 of x images ============
// block = (b, i); 8 images (p). stage1 direct real-DFT, stage2 cfft16.
__global__ __launch_bounds__(256) void k1_xfft(const float* __restrict__ x) {
    int bi = blockIdx.x;
    int b  = bi >> 6;
    int i  = bi & 63;
    __shared__ float  xs2[NP][320];    // [p][c1*20 + c2] (stride-20 c1 blocks)
    __shared__ float2 s1[NP][145];     // [p][c1*9+k2]
    int tid = threadIdx.x;

    // load + transpose: thread tid holds all 8 p for d = tid
    {
        const float4* xg = (const float4*)(x + (size_t)bi * NSYM);
        float4 a = xg[tid * 2], c = xg[tid * 2 + 1];
        int off = tid + (tid >> 4) * 4;     // d -> c1*20 + c2
        xs2[0][off] = a.x; xs2[1][off] = a.y; xs2[2][off] = a.z; xs2[3][off] = a.w;
        xs2[4][off] = c.x; xs2[5][off] = c.y; xs2[6][off] = c.z; xs2[7][off] = c.w;
    }
    __syncthreads();

    // stage1: thread = (k2half, p, c1); direct real DFT (static twiddles)
    {
        int k2h = tid >> 7, p = (tid >> 4) & 7, c1 = tid & 15;
        const float4* gp = (const float4*)&xs2[p][c1 * 20];
        float4 ga = gp[0], gb = gp[1], gc = gp[2], gd = gp[3];
        float g[16] = { ga.x, ga.y, ga.z, ga.w, gb.x, gb.y, gb.z, gb.w,
                        gc.x, gc.y, gc.z, gc.w, gd.x, gd.y, gd.z, gd.w };
        if (k2h == 0) {
            float ar[5] = {0,0,0,0,0}, ai[5] = {0,0,0,0,0};
#pragma unroll
            for (int c2 = 0; c2 < 16; c2++)
#pragma unroll
                for (int t = 0; t < 5; t++) {
                    const int id = ((t * c2) & 15);
                    ar[t] += g[c2] * KC16[id];
                    ai[t] -= g[c2] * KS16F[id];
                }
#pragma unroll
            for (int t = 0; t < 5; t++) s1[p][c1 * 9 + t] = make_float2(ar[t], ai[t]);
        } else {
            float ar[4] = {0,0,0,0}, ai[4] = {0,0,0,0};
#pragma unroll
            for (int c2 = 0; c2 < 16; c2++)
#pragma unroll
                for (int t = 0; t < 4; t++) {
                    const int id = (((t + 5) * c2) & 15);
                    ar[t] += g[c2] * KC16[id];
                    ai[t] -= g[c2] * KS16F[id];
                }
#pragma unroll
            for (int t = 0; t < 4; t++) s1[p][c1 * 9 + 5 + t] = make_float2(ar[t], ai[t]);
        }
    }
    __syncthreads();

    // stage2: item = (p, k2): full 16-pt FFT over c1
    if (tid < 72) {
        int p = tid & 7, k2 = tid >> 3;
        float2 xin[16], Xo[16];
#pragma unroll
        for (int c1 = 0; c1 < 16; c1++) xin[c1] = s1[p][c1 * 9 + k2];
        cfft16<false>(xin, Xo);
#pragma unroll
        for (int k1 = 0; k1 < 16; k1++)
            g_xf[((size_t)(k1 * 9 + k2) * BATCHN + b) * IPD + (i << 3) + p] =
                __floats2half2_rn(Xo[k1].x, Xo[k1].y);
    }
}

// ============ K2: gather + forward rfft2, p-pairs, FFT stage2 ============
// grid = 64*64*4 blocks; block = (f, i, p-pair).
__global__ __launch_bounds__(256) void k2_kfft(const float* __restrict__ kern) {
    int bx = blockIdx.x;
    int pp = bx & 3, fi = bx >> 2;
    int f  = fi >> 6, i = fi & 63;
    __shared__ float krow[NSYM];
    __shared__ unsigned short ptp[2][NSYM];
    __shared__ float  g8[2][NP][320];   // [ph][q][c1*20 + c2]
    __shared__ float2 s1[2][NP][145];
    int tid = threadIdx.x;

    {
        const float4* kg = (const float4*)(kern + (size_t)fi * NSYM);
        ((float4*)krow)[tid * 2]     = kg[tid * 2];
        ((float4*)krow)[tid * 2 + 1] = kg[tid * 2 + 1];
        const uint4* pg = (const uint4*)(g_pt16 + (pp * 2) * NSYM);
        ((uint4*)ptp)[tid]       = pg[tid];
        ((uint4*)ptp)[tid + 256] = pg[tid + 256];
    }
    __syncthreads();

    // gather: 4096 items
#pragma unroll
    for (int it = 0; it < 16; it++) {
        int idx = tid + (it << 8);
        int ph  = idx >> 11;
        int r   = idx & 2047;
        int q   = r & 7, d = r >> 3;
        g8[ph][q][d + (d >> 4) * 4] = krow[ptp[ph][r]];
    }
    __syncthreads();

    // stage1: thread = (ph, q, c1); direct real DFT, all 9 outputs
    {
        int ph = tid >> 7, q = (tid >> 4) & 7, c1 = tid & 15;
        const float4* gp = (const float4*)&g8[ph][q][c1 * 20];
        float4 ga = gp[0], gb = gp[1], gc = gp[2], gd = gp[3];
        float g[16] = { ga.x, ga.y, ga.z, ga.w, gb.x, gb.y, gb.z, gb.w,
                        gc.x, gc.y, gc.z, gc.w, gd.x, gd.y, gd.z, gd.w };
        float ar[9] = {0,0,0,0,0,0,0,0,0}, ai[9] = {0,0,0,0,0,0,0,0,0};
#pragma unroll
        for (int c2 = 0; c2 < 16; c2++)
#pragma unroll
            for (int t = 0; t < 9; t++) {
                const int id = ((t * c2) & 15);
                ar[t] += g[c2] * KC16[id];
                ai[t] -= g[c2] * KS16F[id];
            }
#pragma unroll
        for (int t = 0; t < 9; t++) s1[ph][q][c1 * 9 + t] = make_float2(ar[t], ai[t]);
    }
    __syncthreads();

    // stage2: item = (ph, q, k2): 16-pt FFT over c1 -> k1
    if (tid < 144) {
        int q = tid & 7, v = tid >> 3;
        int k2 = v % 9, ph = v / 9;
        int p  = (pp << 1) + ph;
        float2 xin[16], Xo[16];
#pragma unroll
        for (int c1 = 0; c1 < 16; c1++) xin[c1] = s1[ph][q][c1 * 9 + k2];
        cfft16<false>(xin, Xo);
#pragma unroll
        for (int k1 = 0; k1 < 16; k1++)
            g_kf[((size_t)(k1 * 9 + k2) * IPD + (i << 3) + p) * FQD + (f << 3) + q] =
                __floats2half2_rn(Xo[k1].x, Xo[k1].y);
    }
}

// ============ K3: complex GEMM, fp16 mma, cp.async double buffer ============
__device__ __forceinline__ void mma16(float* d, const uint32_t* a,
                                      uint32_t b0, uint32_t b1) {
    asm volatile(
        "mma.sync.aligned.m16n8k16.row.col.f32.f16.f16.f32 "
        "{%0,%1,%2,%3}, {%4,%5,%6,%7}, {%8,%9}, {%0,%1,%2,%3};\n"
        : "+f"(d[0]), "+f"(d[1]), "+f"(d[2]), "+f"(d[3])
        : "r"(a[0]), "r"(a[1]), "r"(a[2]), "r"(a[3]), "r"(b0), "r"(b1));
}
__device__ __forceinline__ void cpa16(uint32_t s, const void* g) {
    asm volatile("cp.async.cg.shared.global [%0], [%1], 16;" :: "r"(s), "l"(g));
}

__global__ __launch_bounds__(256) void k3_gemm_hmma() {
    int kidx = blockIdx.x;
    int n0   = blockIdx.y << 7;
    __shared__ __align__(16) __half2 Xs[2][64][20];
    __shared__ __align__(16) __half2 Ws[2][16][132];

    int tid = threadIdx.x, wid = tid >> 5, lane = tid & 31;
    int wm = (wid & 3) << 4, wn = (wid >> 2) << 6;
    int gid = lane >> 2, tig = lane & 3;

    const __half2* Xg = g_xf + (size_t)kidx * BATCHN * IPD;
    const __half2* Wg = g_kf + (size_t)kidx * IPD * FQD + n0;

    int xb = tid >> 2, xseg = tid & 3;           // X staging coords
    int wk0 = tid >> 5, wseg0 = tid & 31;        // W staging (2 per thread)
    int wk1 = (tid + 256) >> 5, wseg1 = (tid + 256) & 31;

    float accr[8][4], acci[8][4];
#pragma unroll
    for (int j = 0; j < 8; j++)
#pragma unroll
        for (int c = 0; c < 4; c++) { accr[j][c] = 0.f; acci[j][c] = 0.f; }

    // prefetch chunk 0 into buffer 0
    {
        cpa16((uint32_t)__cvta_generic_to_shared(&Xs[0][xb][xseg * 4]),
              Xg + (size_t)xb * IPD + xseg * 4);
        cpa16((uint32_t)__cvta_generic_to_shared(&Ws[0][wk0][wseg0 * 4]),
              Wg + (size_t)wk0 * FQD + wseg0 * 4);
        cpa16((uint32_t)__cvta_generic_to_shared(&Ws[0][wk1][wseg1 * 4]),
              Wg + (size_t)wk1 * FQD + wseg1 * 4);
        asm volatile("cp.async.commit_group;");
    }

    for (int c = 0; c < 32; c++) {
        int k0 = c << 4;
        if (c + 1 < 32) {
            int nb = (c + 1) & 1, nk0 = (c + 1) << 4;
            cpa16((uint32_t)__cvta_generic_to_shared(&Xs[nb][xb][xseg * 4]),
                  Xg + (size_t)xb * IPD + nk0 + xseg * 4);
            cpa16((uint32_t)__cvta_generic_to_shared(&Ws[nb][wk0][wseg0 * 4]),
                  Wg + (size_t)(nk0 + wk0) * FQD + wseg0 * 4);
            cpa16((uint32_t)__cvta_generic_to_shared(&Ws[nb][wk1][wseg1 * 4]),
                  Wg + (size_t)(nk0 + wk1) * FQD + wseg1 * 4);
        }
        asm volatile("cp.async.commit_group;");
        asm volatile("cp.async.wait_group 1;");
        __syncthreads();

        int cb = c & 1;
        uint32_t arf[4], aif[4];
#pragma unroll
        for (int m = 0; m < 4; m++) {
            int row  = wm + gid + (m & 1) * 8;
            int kpos = 2 * tig + (m >> 1) * 8;
            uint2 lh = *(const uint2*)&Xs[cb][row][kpos];
            arf[m] = __byte_perm(lh.x, lh.y, 0x5410);
            aif[m] = __byte_perm(lh.x, lh.y, 0x7632);
        }
#pragma unroll
        for (int j = 0; j < 8; j++) {
            int col = wn + (j << 3) + gid;
            uint32_t v0 = *(const uint32_t*)&Ws[cb][2 * tig][col];
            uint32_t v1 = *(const uint32_t*)&Ws[cb][2 * tig + 1][col];
            uint32_t v2 = *(const uint32_t*)&Ws[cb][2 * tig + 8][col];
            uint32_t v3 = *(const uint32_t*)&Ws[cb][2 * tig + 9][col];
            uint32_t br0 = __byte_perm(v0, v1, 0x5410), bi0 = __byte_perm(v0, v1, 0x7632);
            uint32_t br1 = __byte_perm(v2, v3, 0x5410), bi1 = __byte_perm(v2, v3, 0x7632);
            uint32_t bn0 = bi0 ^ 0x80008000u, bn1 = bi1 ^ 0x80008000u;
            mma16(accr[j], arf, br0, br1);
            mma16(accr[j], aif, bn0, bn1);
            mma16(acci[j], arf, bi0, bi1);
            mma16(acci[j], aif, br0, br1);
        }
        __syncthreads();
    }

    float2* Yg = g_yf + (size_t)kidx * BATCHN * FQD;
#pragma unroll
    for (int j = 0; j < 8; j++) {
        int nbase = n0 + wn + (j << 3) + 2 * tig;
        int r0 = wm + gid;
        int r1 = wm + gid + 8;
        Yg[(size_t)r0 * FQD + nbase]     = make_float2(accr[j][0], acci[j][0]);
        Yg[(size_t)r0 * FQD + nbase + 1] = make_float2(accr[j][1], acci[j][1]);
        Yg[(size_t)r1 * FQD + nbase]     = make_float2(accr[j][2], acci[j][2]);
        Yg[(size_t)r1 * FQD + nbase + 1] = make_float2(accr[j][3], acci[j][3]);
    }
}

// ============ K4: inverse rfft2 + bias; FFT stageA, hoisted stageB ============
__global__ __launch_bounds__(256) void k4_inv(const float* __restrict__ bias,
                                              float* __restrict__ out) {
    int bf = blockIdx.x;
    int b  = bf >> 6;
    int f  = bf & 63;
    __shared__ float2 ys[NP][145];   // [q][kidx]
    __shared__ float2 T[NP][145];    // [q][c1*9+k2]
    __shared__ float2 tw[16];
    int tid = threadIdx.x;
    if (tid < 16) tw[tid] = make_float2(CTW16[tid], STW16[tid]);

    for (int idx = tid; idx < NP * NFREQ; idx += 256) {
        int kidx = idx >> 3;
        int q    = idx & 7;
        ys[q][kidx] = g_yf[((size_t)kidx * BATCHN + b) * FQD + (f << 3) + q];
    }
    __syncthreads();

    // stageA: item = (q, k2): inverse 16-pt FFT over k1 -> c1
    if (tid < 72) {
        int q = tid & 7, k2 = tid >> 3;
        float2 xin[16], Xo[16];
#pragma unroll
        for (int k1 = 0; k1 < 16; k1++) xin[k1] = ys[q][k1 * 9 + k2];
        cfft16<true>(xin, Xo);
#pragma unroll
        for (int c1 = 0; c1 < 16; c1++) T[q][c1 * 9 + k2] = Xo[c1];
    }
    __syncthreads();

    // stageB: hoisted weighted twiddles, coalesced store
    float bv = bias[f];
    {
        int q  = tid & 7;
        int c2 = (tid >> 3) & 15;
        float wc[9], ws[9];
#pragma unroll
        for (int k2 = 0; k2 < NK2; k2++) {
            float2 w = tw[(k2 * c2) & 15];
            float wt = (k2 == 0 || k2 == 8) ? (1.f / 256.f) : (2.f / 256.f);
            wc[k2] = wt * w.x;
            ws[k2] = wt * w.y;
        }
#pragma unroll
        for (int u = 0; u < 8; u++) {
            int c1 = u * 2 + (tid >> 7);
            float acc = bv;
#pragma unroll
            for (int k2 = 0; k2 < NK2; k2++) {
                float2 v = T[q][c1 * 9 + k2];
                acc += v.x * wc[k2] - v.y * ws[k2];
            }
            out[(size_t)bf * NSYM + u * 256 + tid] = acc;
        }
    }
}

// ============ launch ============
extern "C" void kernel_launch(void* const* d_in, const int* in_sizes, int n_in,
                              void* d_out, int out_size) {
    const float* x    = (const float*)d_in[0];
    const float* kern = (const float*)d_in[1];
    const float* bias = (const float*)d_in[2];
    const void*  pt   = d_in[3];              // int32 or int64 — k0 autodetects
    float*       out  = (float*)d_out;

    k0_pt<<<1, 256>>>(pt);
    k1_xfft<<<BATCHN * INF, 256>>>(x);
    k2_kfft<<<FEAT * INF * 4, 256>>>(kern);
    dim3 g3(NFREQ, FQD / 128);
    k3_gemm_hmma<<<g3, 256>>>();
    k4_inv<<<BATCHN * FEAT, 256>>>(bias, out);
}